// round 3
// baseline (speedup 1.0000x reference)
#include <cuda_runtime.h>
#include <cuda_bf16.h>

// AngleTensor: out[b,i,j,k] = mask * acos( (p_j-p_i)·(p_k-p_i) / (d_ij*d_ik) )
// B=8, N=128. Output 8*128^3 fp32 = 67MB -> store-bound target ~10-14us.
//
// Strategy: one block per (b,i). Precompute normalized diff vectors
// u_j = (p_j - p_i)/d_ij once in shared (kills the per-element divide);
// then cos(theta_jk) = u_j . u_k  (3 FMA). Mask before acosf; clamp to
// [-1,1] against rounding. Coalesced float4 stores, one warp per j-row.

#define AT_N 128

__global__ __launch_bounds__(256, 8)
void AngleTensor_69767448756825_kernel(const float* __restrict__ pos,
                                       const float* __restrict__ dist,
                                       float* __restrict__ out) {
    const int i = blockIdx.x;   // center point index
    const int b = blockIdx.y;   // batch
    const int t = threadIdx.x;  // 0..255

    __shared__ float ux[AT_N], uy[AT_N], uz[AT_N], dd[AT_N];

    const float* pb = pos + (size_t)b * AT_N * 3;
    const float pix = pb[i * 3 + 0];
    const float piy = pb[i * 3 + 1];
    const float piz = pb[i * 3 + 2];

    if (t < AT_N) {
        float dx = pb[t * 3 + 0] - pix;
        float dy = pb[t * 3 + 1] - piy;
        float dz = pb[t * 3 + 2] - piz;
        float d  = dist[((size_t)b * AT_N + i) * AT_N + t];
        // Normalized diff. d==0 only when t==i (masked later) -> u=0 avoids NaN.
        float inv = (d > 0.0f) ? (1.0f / d) : 0.0f;
        ux[t] = dx * inv;
        uy[t] = dy * inv;
        uz[t] = dz * inv;
        dd[t] = d;
    }
    __syncthreads();

    float* outp = out + ((size_t)b * AT_N + i) * AT_N * AT_N;

    // N*N floats = 16384 = 4096 float4; 256 threads -> 16 iterations.
    // Within one iteration a warp covers exactly one j-row (32 float4 = 128 k),
    // so u_j loads are warp-broadcast and u_k loads are lane-linear (no conflicts).
    #pragma unroll
    for (int it = 0; it < (AT_N * AT_N / 4) / 256; ++it) {
        const int idx4 = t + it * 256;
        const int j    = idx4 >> 5;          // 32 float4 per row
        const int k0   = (idx4 & 31) << 2;

        const float ujx = ux[j];
        const float ujy = uy[j];
        const float ujz = uz[j];
        const float dj  = dd[j];
        const bool  ji  = (j != i);

        float4 r;
        float* rp = &r.x;
        #pragma unroll
        for (int c = 0; c < 4; ++c) {
            const int k = k0 + c;
            float cn  = ujx * ux[k] + ujy * uy[k] + ujz * uz[k];
            float mag = dj * dd[k];
            // reference: divide by 1 instead of mag when mag < EPS
            float cosv = (mag < 1e-10f) ? (cn * mag) : cn;
            cosv = fminf(1.0f, fmaxf(-1.0f, cosv));
            const bool m = ji && (k != i) && (j != k);
            rp[c] = m ? acosf(cosv) : 0.0f;
        }
        reinterpret_cast<float4*>(outp)[idx4] = r;  // 128B coalesced per warp
    }
}

extern "C" void kernel_launch(void* const* d_in, const int* in_sizes, int n_in,
                              void* d_out, int out_size) {
    // B from the output contract: out is (B, N, N, N) fp32.
    const int B = out_size / (AT_N * AT_N * AT_N);

    // Bind inputs by size, not order: positions = B*N*3, dist = B*N*N.
    const float* pos  = nullptr;
    const float* dist = nullptr;
    for (int a = 0; a < n_in; ++a) {
        if (in_sizes[a] == B * AT_N * 3)          pos  = (const float*)d_in[a];
        else if (in_sizes[a] == B * AT_N * AT_N)  dist = (const float*)d_in[a];
    }
    if (!pos)  pos  = (const float*)d_in[0];
    if (!dist) dist = (const float*)d_in[n_in > 1 ? 1 : 0];

    float* out = (float*)d_out;
    dim3 grid(AT_N, B);
    AngleTensor_69767448756825_kernel<<<grid, 256>>>(pos, dist, out);
}

// round 4
// speedup vs baseline: 1.6274x; 1.6274x over previous
#include <cuda_runtime.h>
#include <cuda_bf16.h>

// AngleTensor: out[b,i,j,k] = mask * acos( u_j . u_k ), u_t = (p_t - p_i)/|p_t - p_i|
// B=8, N=128. Output fits in L2 -> no HBM floor; kernel is issue-bound.
// This version: custom polynomial acos, no dist_matrix, value-based masking,
// register-resident k-quads, one broadcast LDS.128 per row.

#define AT_N 128

__device__ __forceinline__ float fast_acos(float x) {
    // |abs err| <= 6.7e-5 (A&S 4.4.45); exact sqrt(1-x) factor keeps rel err
    // ~5e-5 even as angle -> 0.
    float y  = fmaxf(1.0f - fabsf(x), 0.0f);   // 1-|x|, clamped vs rounding >1
    float s;
    asm("sqrt.approx.f32 %0, %1;" : "=f"(s) : "f"(y));
    float ax = 1.0f - y;                        // == min(|x|,1)
    float p  = fmaf(fmaf(fmaf(-0.0187293f, ax, 0.0742610f),
                         ax, -0.2121144f), ax, 1.5707288f);
    float r  = s * p;
    return (x < 0.0f) ? (3.14159265358979f - r) : r;
}

__global__ __launch_bounds__(256)
void AngleTensor_69767448756825_kernel(const float* __restrict__ pos,
                                       float* __restrict__ out) {
    const int i    = blockIdx.x;    // center point
    const int b    = blockIdx.y;    // batch
    const int t    = threadIdx.x;   // 0..255
    const int lane = t & 31;
    const int w    = t >> 5;        // warp 0..7

    __shared__ float4 su[AT_N];     // {ux, uy, uz, wk}

    const float* pb = pos + (size_t)b * AT_N * 3;
    const float pix = pb[i * 3 + 0];
    const float piy = pb[i * 3 + 1];
    const float piz = pb[i * 3 + 2];

    if (t < AT_N) {
        float dx = pb[t * 3 + 0] - pix;
        float dy = pb[t * 3 + 1] - piy;
        float dz = pb[t * 3 + 2] - piz;
        float n2 = dx * dx + dy * dy + dz * dz;
        float inv = (n2 > 0.0f) ? rsqrtf(n2) : 0.0f;   // t==i -> u=0
        float wt  = (t == i) ? 0.0f : 1.0f;
        su[t] = make_float4(dx * inv, dy * inv, dz * inv, wt);
    }
    __syncthreads();

    // Each lane owns k-quad {4*lane .. 4*lane+3} in registers for all rows.
    const int k0 = lane << 2;
    const float4 ka = su[k0 + 0];
    const float4 kb = su[k0 + 1];
    const float4 kc = su[k0 + 2];
    const float4 kd = su[k0 + 3];

    float* outp = out + ((size_t)b * AT_N + i) * AT_N * AT_N;

    // Warp w handles rows j = w*16 .. w*16+15; one STG.128 per row per lane.
    #pragma unroll
    for (int it = 0; it < AT_N / 8; ++it) {
        const int j = w * (AT_N / 8) + it;
        const float4 uj = su[j];            // broadcast LDS.128

        float4 r;
        if (uj.w == 0.0f) {                 // j == i: warp-uniform zero row
            r = make_float4(0.f, 0.f, 0.f, 0.f);
        } else {
            float c0 = uj.x * ka.x + uj.y * ka.y + uj.z * ka.z;
            float c1 = uj.x * kb.x + uj.y * kb.y + uj.z * kb.z;
            float c2 = uj.x * kc.x + uj.y * kc.y + uj.z * kc.z;
            float c3 = uj.x * kd.x + uj.y * kd.y + uj.z * kd.z;
            r.x = fast_acos(c0) * ka.w;     // ka.w==0 kills k==i
            r.y = fast_acos(c1) * kb.w;
            r.z = fast_acos(c2) * kc.w;
            r.w = fast_acos(c3) * kd.w;
            const unsigned jj = (unsigned)(j - k0);
            if (jj < 4u) (&r.x)[jj] = 0.0f; // exact zero at j==k
        }
        reinterpret_cast<float4*>(outp)[j * (AT_N / 4) + lane] = r;
    }
}

extern "C" void kernel_launch(void* const* d_in, const int* in_sizes, int n_in,
                              void* d_out, int out_size) {
    const int B = out_size / (AT_N * AT_N * AT_N);

    // positions = (B, N, 3); bind by size so input order can't bite us.
    const float* pos = nullptr;
    for (int a = 0; a < n_in; ++a)
        if (in_sizes[a] == B * AT_N * 3) pos = (const float*)d_in[a];
    if (!pos) pos = (const float*)d_in[0];

    dim3 grid(AT_N, B);
    AngleTensor_69767448756825_kernel<<<grid, 256>>>(pos, (float*)d_out);
}

// round 5
// speedup vs baseline: 1.8548x; 1.1397x over previous
#include <cuda_runtime.h>
#include <cuda_bf16.h>

// AngleTensor: out[b,i,j,k] = mask * acos( u_j . u_k ), u_t = (p_t - p_i)/|p_t-p_i|
// Issue-bound (output L2-resident, DRAM 5%). This round: Blackwell f32x2 packed
// math for dot / acos-poly / reflect / mask -> ~25% fewer warp instructions.

#define AT_N 128
typedef unsigned long long u64;

__device__ __forceinline__ u64 pk(float lo, float hi) {
    u64 r; asm("mov.b64 %0, {%1, %2};" : "=l"(r) : "f"(lo), "f"(hi)); return r;
}
__device__ __forceinline__ float2 upk(u64 a) {
    float2 r; asm("mov.b64 {%0, %1}, %2;" : "=f"(r.x), "=f"(r.y) : "l"(a)); return r;
}
__device__ __forceinline__ u64 fma2(u64 a, u64 b, u64 c) {
    u64 d; asm("fma.rn.f32x2 %0, %1, %2, %3;" : "=l"(d) : "l"(a), "l"(b), "l"(c)); return d;
}
__device__ __forceinline__ u64 mul2(u64 a, u64 b) {
    u64 d; asm("mul.rn.f32x2 %0, %1, %2;" : "=l"(d) : "l"(a), "l"(b)); return d;
}
__device__ __forceinline__ float sqapx(float x) {
    float s; asm("sqrt.approx.f32 %0, %1;" : "=f"(s) : "f"(x)); return s;
}

__global__ __launch_bounds__(256)
void AngleTensor_69767448756825_kernel(const float* __restrict__ pos,
                                       float* __restrict__ out) {
    const int i    = blockIdx.x;
    const int b    = blockIdx.y;
    const int t    = threadIdx.x;
    const int lane = t & 31;
    const int w    = t >> 5;

    __shared__ float4 su[AT_N];   // {ux, uy, uz, weight(k!=i)}

    const float* pb = pos + (size_t)b * AT_N * 3;
    const float pix = pb[i * 3 + 0];
    const float piy = pb[i * 3 + 1];
    const float piz = pb[i * 3 + 2];

    if (t < AT_N) {
        float dx = pb[t * 3 + 0] - pix;
        float dy = pb[t * 3 + 1] - piy;
        float dz = pb[t * 3 + 2] - piz;
        float n2 = dx * dx + dy * dy + dz * dz;
        float inv = (n2 > 0.0f) ? rsqrtf(n2) : 0.0f;   // t==i -> u=0
        float wt  = (t == i) ? 0.0f : 1.0f;
        su[t] = make_float4(dx * inv, dy * inv, dz * inv, wt);
    }
    __syncthreads();

    // Lane-owned k-quad, repacked as f32x2 pairs.
    const int k0 = lane << 2;
    const float4 q0 = su[k0 + 0];
    const float4 q1 = su[k0 + 1];
    const float4 q2 = su[k0 + 2];
    const float4 q3 = su[k0 + 3];
    const u64 kx01 = pk(q0.x, q1.x), kx23 = pk(q2.x, q3.x);
    const u64 ky01 = pk(q0.y, q1.y), ky23 = pk(q2.y, q3.y);
    const u64 kz01 = pk(q0.z, q1.z), kz23 = pk(q2.z, q3.z);
    const u64 w01  = pk(q0.w, q1.w), w23  = pk(q2.w, q3.w);

    // Packed constants (hoisted into registers once).
    const u64 ABSM = 0x7fffffff7fffffffull;
    const u64 SGNB = 0x8000000080000000ull;
    const u64 ONEF = 0x3f8000003f800000ull;   // 1.0f pair (for sign LOP3)
    const u64 NEG1 = pk(-1.0f, -1.0f);
    const u64 ONE2 = pk(1.0f, 1.0f);
    const u64 A3 = pk(-0.0187293f, -0.0187293f);
    const u64 A2 = pk( 0.0742610f,  0.0742610f);
    const u64 A1 = pk(-0.2121144f, -0.2121144f);
    const u64 A0 = pk( 1.5707288f,  1.5707288f);
    const u64 HP  = pk( 1.57079632679f,  1.57079632679f);
    const u64 NHP = pk(-1.57079632679f, -1.57079632679f);

    float4* orow = reinterpret_cast<float4*>(
        out + ((size_t)b * AT_N + i) * AT_N * AT_N);

    #pragma unroll 4
    for (int it = 0; it < AT_N / 8; ++it) {
        const int j = w * (AT_N / 8) + it;
        const float4 uj = su[j];                       // broadcast LDS.128
        const u64 jx = pk(uj.x, uj.x);
        const u64 jy = pk(uj.y, uj.y);
        const u64 jz = pk(uj.z, uj.z);

        // cos = u_j . u_k  (packed, 3 ops per 2 elements)
        u64 c01 = fma2(jz, kz01, fma2(jy, ky01, mul2(jx, kx01)));
        u64 c23 = fma2(jz, kz23, fma2(jy, ky23, mul2(jx, kx23)));

        // |c| and y = 1-|c| (packed); clamp + sqrt scalar (MUFU anyway)
        u64 ax01 = c01 & ABSM, ax23 = c23 & ABSM;
        float2 y01 = upk(fma2(ax01, NEG1, ONE2));
        float2 y23 = upk(fma2(ax23, NEG1, ONE2));
        u64 s01 = pk(sqapx(fmaxf(y01.x, 0.0f)), sqapx(fmaxf(y01.y, 0.0f)));
        u64 s23 = pk(sqapx(fmaxf(y23.x, 0.0f)), sqapx(fmaxf(y23.y, 0.0f)));

        // poly(|c|) packed (A&S 4.4.45, abs err <= 6.7e-5)
        u64 p01 = fma2(fma2(fma2(A3, ax01, A2), ax01, A1), ax01, A0);
        u64 p23 = fma2(fma2(fma2(A3, ax23, A2), ax23, A1), ax23, A0);

        // branchless reflect: sgn = +-1.0f from sign(c); r = s*p*sgn + (pi/2 - sgn*pi/2)
        u64 sg01 = (c01 & SGNB) | ONEF;
        u64 sg23 = (c23 & SGNB) | ONEF;
        u64 r01 = fma2(mul2(s01, p01), sg01, fma2(sg01, NHP, HP));
        u64 r23 = fma2(mul2(s23, p23), sg23, fma2(sg23, NHP, HP));

        // mask: (k!=i) * (j!=i)
        const u64 rw = pk(uj.w, uj.w);
        r01 = mul2(r01, mul2(w01, rw));
        r23 = mul2(r23, mul2(w23, rw));

        float2 g01 = upk(r01), g23 = upk(r23);
        float4 r4 = make_float4(g01.x, g01.y, g23.x, g23.y);

        // exact zero on the j==k diagonal (component index compile-time per replica)
        if ((j >> 2) == lane) {
            if      ((it & 3) == 0) r4.x = 0.0f;
            else if ((it & 3) == 1) r4.y = 0.0f;
            else if ((it & 3) == 2) r4.z = 0.0f;
            else                    r4.w = 0.0f;
        }

        orow[j * (AT_N / 4) + lane] = r4;              // STG.128 coalesced
    }
}

extern "C" void kernel_launch(void* const* d_in, const int* in_sizes, int n_in,
                              void* d_out, int out_size) {
    const int B = out_size / (AT_N * AT_N * AT_N);

    const float* pos = nullptr;
    for (int a = 0; a < n_in; ++a)
        if (in_sizes[a] == B * AT_N * 3) pos = (const float*)d_in[a];
    if (!pos) pos = (const float*)d_in[0];

    dim3 grid(AT_N, B);
    AngleTensor_69767448756825_kernel<<<grid, 256>>>(pos, (float*)d_out);
}